// round 3
// baseline (speedup 1.0000x reference)
#include <cuda_runtime.h>
#include <cstdint>
#include <math.h>

#define B_    2
#define N_    65536
#define K_    4
#define HID_  64
#define C_    128
#define NPB   16          // points per block (k_zr / k_q)

typedef unsigned long long u64;

// Scratch (static device globals; no runtime allocation)
__device__ float g_hx[(size_t)B_ * N_ * C_];     // [b][n][c]  c<64: h, c>=64: x
__device__ float g_rh[(size_t)B_ * N_ * HID_];   // [b][n][o]  r*h (compact)
__device__ float g_z [(size_t)B_ * N_ * HID_];   // [b][n][o]  sigmoid(z)
__device__ u64   g_wTp[3 * C_ * HID_];           // [g][c][o]  packed (w,w)

__device__ __forceinline__ u64 pk2(float a, float b) {
    u64 r; asm("mov.b64 %0, {%1,%2};" : "=l"(r) : "f"(a), "f"(b)); return r;
}
__device__ __forceinline__ void up2(u64 v, float& a, float& b) {
    asm("mov.b64 {%0,%1}, %2;" : "=f"(a), "=f"(b) : "l"(v));
}
__device__ __forceinline__ void fma2(u64& d, u64 a, u64 b) {
    asm("fma.rn.f32x2 %0, %1, %2, %0;" : "+l"(d) : "l"(a), "l"(b));
}
__device__ __forceinline__ float sigm(float v) { return 1.0f / (1.0f + __expf(-v)); }

// ---------------------------------------------------------------------------
// Packed transposed weights: g_wTp[g][c][o] = (w_out[o][c], w_out[o][c])
// ---------------------------------------------------------------------------
__global__ void k_wT(const float* __restrict__ wz, const float* __restrict__ wr,
                     const float* __restrict__ wq) {
    int i = blockIdx.x * blockDim.x + threadIdx.x;
    if (i >= 3 * C_ * HID_) return;
    int g = i / (C_ * HID_);
    int r = i - g * (C_ * HID_);
    int c = r / HID_;
    int o = r - c * HID_;
    const float* w = (g == 0) ? wz : ((g == 1) ? wr : wq);
    float v = w[o * C_ + c];
    g_wTp[i] = pk2(v, v);
}

// ---------------------------------------------------------------------------
// Build hx_t[b][n][c] = (c<64 ? h[b][c][n] : x[b][c-64][n])   (32-pt tiles)
// ---------------------------------------------------------------------------
__global__ __launch_bounds__(256) void k_tr(const float* __restrict__ h,
                                            const float* __restrict__ x) {
    __shared__ float t[C_][33];
    const int b  = blockIdx.x >> 11;
    const int n0 = (blockIdx.x & 2047) * 32;
    const int tid  = threadIdx.x;
    const int lane = tid & 31;
    const int w    = tid >> 5;

    for (int r = w; r < C_; r += 8) {
        const float* src = (r < HID_)
            ? (h + ((size_t)(b * HID_ + r)) * N_)
            : (x + ((size_t)(b * HID_ + (r - HID_))) * N_);
        t[r][lane] = src[n0 + lane];
    }
    __syncthreads();

    const int nn = tid >> 3;
    const int q0 = tid & 7;
    float* dst = g_hx + ((size_t)(b * N_ + n0 + nn)) * C_;
#pragma unroll
    for (int k = 0; k < 4; k++) {
        int c = 4 * (q0 + 8 * k);
        float4 v = make_float4(t[c][nn], t[c + 1][nn], t[c + 2][nn], t[c + 3][nn]);
        *(float4*)(dst + c) = v;
    }
}

// ---------------------------------------------------------------------------
// ZR kernel: 16 points per block, 256 threads.
// Phase 1: gather (LDG.64/thread, warp=half row) + moment trick -> agg[2][C][pt]
// Phase 2: packed-f32x2 matvec for both gates; z -> zsm, r*h -> rsm
// Phase 3: coalesced float4 writes of g_z and g_rh.
// ---------------------------------------------------------------------------
__global__ __launch_bounds__(256, 4) void k_zr(
    const float* __restrict__ xyz, const int* __restrict__ knn,
    const float* __restrict__ wzp, const float* __restrict__ bzp,
    const float* __restrict__ bzo,
    const float* __restrict__ wrp, const float* __restrict__ brp,
    const float* __restrict__ bro) {
    __shared__ __align__(16) float agg[2][C_][20];
    __shared__ float hsm[NPB][65];
    __shared__ float zsm[NPB][65];
    __shared__ float rsm[NPB][65];
    __shared__ float srel[NPB][12];
    __shared__ int   sidx[NPB][4];

    const int b   = blockIdx.x >> 12;
    const int n0  = (blockIdx.x & 4095) * NPB;
    const int tid = threadIdx.x;
    const int lane = tid & 31;
    const int w    = tid >> 5;

    // Stage h rows (for r*h), neighbor idx, relative coords
    for (int i = tid; i < NPB * HID_; i += 256) {
        int r = i >> 6, c = i & 63;
        hsm[r][c] = g_hx[((size_t)(b * N_ + n0 + r)) * C_ + c];
    }
    if (tid < NPB * 4) {
        int pt = tid >> 2, j = tid & 3;
        int n  = n0 + pt;
        int m  = knn[((size_t)b * N_ + n) * K_ + j];
        sidx[pt][j] = m;
        const float* xb = xyz + (size_t)b * 3 * N_;
#pragma unroll
        for (int d = 0; d < 3; d++)
            srel[pt][j * 3 + d] = xb[(size_t)d * N_ + m] - xb[(size_t)d * N_ + n];
    }
    __syncthreads();

    // Phase 1: gather + moments + both gates
    {
        const float* hxb = g_hx + (size_t)b * N_ * C_;
#pragma unroll
        for (int u = 0; u < 4; u++) {
            const int idx  = w + 8 * u;       // 32 (pt, half) combos
            const int pt   = idx >> 1;
            const int half = idx & 1;
            const int c0   = half * HID_ + 2 * lane;

            int m[4];
#pragma unroll
            for (int j = 0; j < 4; j++) m[j] = sidx[pt][j];
            float2 gv[4];
#pragma unroll
            for (int j = 0; j < 4; j++)
                gv[j] = *(const float2*)(hxb + (size_t)m[j] * C_ + c0);

            float m0a = 0.f, m1a = 0.f, m2a = 0.f, m3a = 0.f;
            float m0b = 0.f, m1b = 0.f, m2b = 0.f, m3b = 0.f;
#pragma unroll
            for (int j = 0; j < 4; j++) {
                float r0 = srel[pt][3 * j + 0];
                float r1 = srel[pt][3 * j + 1];
                float r2 = srel[pt][3 * j + 2];
                float ga = gv[j].x, gb = gv[j].y;
                m1a = fmaf(r0, ga, m1a); m2a = fmaf(r1, ga, m2a);
                m3a = fmaf(r2, ga, m3a); m0a += ga;
                m1b = fmaf(r0, gb, m1b); m2b = fmaf(r1, gb, m2b);
                m3b = fmaf(r2, gb, m3b); m0b += gb;
            }
#pragma unroll
            for (int g2 = 0; g2 < 2; g2++) {
                const float* wp = g2 ? wrp : wzp;
                const float* bp = g2 ? brp : bzp;
                float w0 = wp[3 * c0], w1 = wp[3 * c0 + 1], w2 = wp[3 * c0 + 2];
                float bb = bp[c0];
                agg[g2][c0][pt] =
                    fmaf(w0, m1a, fmaf(w1, m2a, fmaf(w2, m3a, bb * m0a)));
                int c1 = c0 + 1;
                float u0 = wp[3 * c1], u1 = wp[3 * c1 + 1], u2 = wp[3 * c1 + 2];
                float cb = bp[c1];
                agg[g2][c1][pt] =
                    fmaf(u0, m1b, fmaf(u1, m2b, fmaf(u2, m3b, cb * m0b)));
            }
        }
    }
    __syncthreads();

    // Phase 2: matvec, 4 point-pairs per thread
    {
        const int g2  = w >> 2;
        const int sub = w & 3;
        const int o   = lane + 32 * (sub & 1);
        const int p0  = 8 * (sub >> 1);
        const u64* wp = g_wTp + (size_t)g2 * C_ * HID_ + o;
        const float bb = (g2 ? bro : bzo)[o];

        u64 a0 = pk2(bb, bb), a1 = a0, a2 = a0, a3 = a0;
#pragma unroll 4
        for (int c = 0; c < C_; c++) {
            float4 A  = *(const float4*)&agg[g2][c][p0];
            float4 Bv = *(const float4*)&agg[g2][c][p0 + 4];
            u64 W = wp[(size_t)c * HID_];
            fma2(a0, pk2(A.x, A.y), W);
            fma2(a1, pk2(A.z, A.w), W);
            fma2(a2, pk2(Bv.x, Bv.y), W);
            fma2(a3, pk2(Bv.z, Bv.w), W);
        }
        float v[8];
        up2(a0, v[0], v[1]); up2(a1, v[2], v[3]);
        up2(a2, v[4], v[5]); up2(a3, v[6], v[7]);
        if (g2 == 0) {
#pragma unroll
            for (int k = 0; k < 8; k++) zsm[p0 + k][o] = sigm(v[k]);
        } else {
#pragma unroll
            for (int k = 0; k < 8; k++) {
                float r = sigm(v[k]);
                rsm[p0 + k][o] = r * hsm[p0 + k][o];
            }
        }
    }
    __syncthreads();

    // Phase 3: coalesced writes
    {
        const int row = tid >> 4;
        const int q   = tid & 15;
        size_t base = ((size_t)(b * N_ + n0 + row)) * HID_ + 4 * q;
        float4 vz = make_float4(zsm[row][4 * q], zsm[row][4 * q + 1],
                                zsm[row][4 * q + 2], zsm[row][4 * q + 3]);
        *(float4*)(g_z + base) = vz;
        float4 vr = make_float4(rsm[row][4 * q], rsm[row][4 * q + 1],
                                rsm[row][4 * q + 2], rsm[row][4 * q + 3]);
        *(float4*)(g_rh + base) = vr;
    }
}

// ---------------------------------------------------------------------------
// Q kernel: 16 points per block, 256 threads. Gathers r*h (compact) || x (from
// g_hx), q gate matvec, GRU combine, coalesced output.
// ---------------------------------------------------------------------------
__global__ __launch_bounds__(256, 5) void k_q(
    const float* __restrict__ xyz, const int* __restrict__ knn,
    const float* __restrict__ wqp, const float* __restrict__ bqp,
    const float* __restrict__ bqo, float* __restrict__ out) {
    __shared__ __align__(16) float agg[C_][20];
    __shared__ float hsm[NPB][65];
    __shared__ float zsm[NPB][65];
    __shared__ float osm[NPB][65];
    __shared__ float srel[NPB][12];
    __shared__ int   sidx[NPB][4];

    const int b   = blockIdx.x >> 12;
    const int n0  = (blockIdx.x & 4095) * NPB;
    const int tid = threadIdx.x;
    const int lane = tid & 31;
    const int w    = tid >> 5;

    for (int i = tid; i < NPB * HID_; i += 256) {
        int r = i >> 6, c = i & 63;
        size_t nb = (size_t)(b * N_ + n0 + r);
        hsm[r][c] = g_hx[nb * C_ + c];
        zsm[r][c] = g_z [nb * HID_ + c];
    }
    if (tid < NPB * 4) {
        int pt = tid >> 2, j = tid & 3;
        int n  = n0 + pt;
        int m  = knn[((size_t)b * N_ + n) * K_ + j];
        sidx[pt][j] = m;
        const float* xb = xyz + (size_t)b * 3 * N_;
#pragma unroll
        for (int d = 0; d < 3; d++)
            srel[pt][j * 3 + d] = xb[(size_t)d * N_ + m] - xb[(size_t)d * N_ + n];
    }
    __syncthreads();

    // Phase 1: gather + direct depthwise agg (single gate)
    {
        const float* rhb = g_rh + (size_t)b * N_ * HID_ + 2 * lane;
        const float* xxb = g_hx + (size_t)b * N_ * C_ + HID_ + 2 * lane;
#pragma unroll
        for (int u = 0; u < 4; u++) {
            const int idx  = w + 8 * u;
            const int pt   = idx >> 1;
            const int half = idx & 1;
            const int c0   = half * HID_ + 2 * lane;

            int m[4];
#pragma unroll
            for (int j = 0; j < 4; j++) m[j] = sidx[pt][j];
            float2 gv[4];
            if (half == 0) {
#pragma unroll
                for (int j = 0; j < 4; j++)
                    gv[j] = *(const float2*)(rhb + (size_t)m[j] * HID_);
            } else {
#pragma unroll
                for (int j = 0; j < 4; j++)
                    gv[j] = *(const float2*)(xxb + (size_t)m[j] * C_);
            }

            float w0 = wqp[3 * c0],     w1 = wqp[3 * c0 + 1], w2 = wqp[3 * c0 + 2];
            float u0 = wqp[3 * c0 + 3], u1 = wqp[3 * c0 + 4], u2 = wqp[3 * c0 + 5];
            float ba = bqp[c0], bb = bqp[c0 + 1];
            float a0 = 0.f, a1 = 0.f;
#pragma unroll
            for (int j = 0; j < 4; j++) {
                float r0 = srel[pt][3 * j + 0];
                float r1 = srel[pt][3 * j + 1];
                float r2 = srel[pt][3 * j + 2];
                float wa = fmaf(w0, r0, fmaf(w1, r1, fmaf(w2, r2, ba)));
                float wb = fmaf(u0, r0, fmaf(u1, r1, fmaf(u2, r2, bb)));
                a0 = fmaf(wa, gv[j].x, a0);
                a1 = fmaf(wb, gv[j].y, a1);
            }
            agg[c0][pt]     = a0;
            agg[c0 + 1][pt] = a1;
        }
    }
    __syncthreads();

    // Phase 2: matvec + tanh + GRU combine -> osm
    {
        const int o  = lane + 32 * (w & 1);
        const int p0 = 4 * (w >> 1);
        const u64* wp = g_wTp + (size_t)2 * C_ * HID_ + o;
        const float bb = bqo[o];

        u64 a0 = pk2(bb, bb), a1 = a0;
#pragma unroll 4
        for (int c = 0; c < C_; c++) {
            float4 A = *(const float4*)&agg[c][p0];
            u64 W = wp[(size_t)c * HID_];
            fma2(a0, pk2(A.x, A.y), W);
            fma2(a1, pk2(A.z, A.w), W);
        }
        float v[4];
        up2(a0, v[0], v[1]); up2(a1, v[2], v[3]);
#pragma unroll
        for (int k = 0; k < 4; k++) {
            int p = p0 + k;
            float z  = zsm[p][o];
            float hh = hsm[p][o];
            float qv = tanhf(v[k]);
            osm[p][o] = fmaf(z, qv - hh, hh);   // (1-z)h + z q
        }
    }
    __syncthreads();

    // Phase 3: coalesced output out[b][o][n0..n0+15]
    {
        const int o = tid >> 2;
        const int q = tid & 3;
        float4 v = make_float4(osm[4 * q][o], osm[4 * q + 1][o],
                               osm[4 * q + 2][o], osm[4 * q + 3][o]);
        *(float4*)(out + ((size_t)(b * HID_ + o)) * N_ + n0 + 4 * q) = v;
    }
}

// ---------------------------------------------------------------------------
extern "C" void kernel_launch(void* const* d_in, const int* in_sizes, int n_in,
                              void* d_out, int out_size) {
    const float* xyz = (const float*)d_in[0];
    const float* h   = (const float*)d_in[1];
    const float* x   = (const float*)d_in[2];
    const int*   knn = (const int*)  d_in[3];
    const float* wzp = (const float*)d_in[4];
    const float* bzp = (const float*)d_in[5];
    const float* wzo = (const float*)d_in[6];
    const float* bzo = (const float*)d_in[7];
    const float* wrp = (const float*)d_in[8];
    const float* brp = (const float*)d_in[9];
    const float* wro = (const float*)d_in[10];
    const float* bro = (const float*)d_in[11];
    const float* wqp = (const float*)d_in[12];
    const float* bqp = (const float*)d_in[13];
    const float* wqo = (const float*)d_in[14];
    const float* bqo = (const float*)d_in[15];
    float* out = (float*)d_out;

    k_wT<<<(3 * C_ * HID_ + 255) / 256, 256>>>(wzo, wro, wqo);
    k_tr<<<(B_ * N_) / 32, 256>>>(h, x);
    k_zr<<<(B_ * N_) / NPB, 256>>>(xyz, knn, wzp, bzp, bzo, wrp, brp, bro);
    k_q <<<(B_ * N_) / NPB, 256>>>(xyz, knn, wqp, bqp, bqo, out);
}

// round 4
// speedup vs baseline: 1.4294x; 1.4294x over previous
#include <cuda_runtime.h>
#include <cstdint>
#include <math.h>

#define B_    2
#define N_    65536
#define HID_  64
#define C_    128
#define NPB   32
#define AP    132     // aggT row pad in floats (16B-aligned rows)

typedef unsigned long long u64;

// Scratch (static device globals)
__device__ float  g_hx[(size_t)B_ * N_ * C_];    // [b][n][c] c<64: h, c>=64: x
__device__ float  g_rh[(size_t)B_ * N_ * HID_];  // [b][n][o] r*h
__device__ float  g_z [(size_t)B_ * N_ * HID_];  // [b][n][o] sigmoid(z)
__device__ u64    g_wQ [3 * 64 * 64];            // [g][cp][o] = (w[2cp][o], w[2cp+1][o])
__device__ float4 g_wp4[3 * C_];                 // [g][c] = (w0,w1,w2,bias)

union F4 { float4 v; u64 q[2]; float f[4]; };

__device__ __forceinline__ u64 pk2(float a, float b) {
    u64 r; asm("mov.b64 %0, {%1,%2};" : "=l"(r) : "f"(a), "f"(b)); return r;
}
__device__ __forceinline__ void up2(u64 v, float& a, float& b) {
    asm("mov.b64 {%0,%1}, %2;" : "=f"(a), "=f"(b) : "l"(v));
}
__device__ __forceinline__ void fma2(u64& d, u64 a, u64 b) {
    asm("fma.rn.f32x2 %0, %1, %2, %0;" : "+l"(d) : "l"(a), "l"(b));
}
__device__ __forceinline__ float sigm(float v) { return 1.0f / (1.0f + __expf(-v)); }

// ---------------------------------------------------------------------------
// Weight prep: packed channel-pair matvec weights + packed position weights
// ---------------------------------------------------------------------------
__global__ void k_wT(const float* __restrict__ wz, const float* __restrict__ wr,
                     const float* __restrict__ wq,
                     const float* __restrict__ wzp, const float* __restrict__ bzp,
                     const float* __restrict__ wrp, const float* __restrict__ brp,
                     const float* __restrict__ wqp, const float* __restrict__ bqp) {
    int i = blockIdx.x * blockDim.x + threadIdx.x;
    if (i < 3 * 64 * 64) {
        int g  = i >> 12;
        int r  = i & 4095;
        int cp = r >> 6;
        int o  = r & 63;
        const float* w = (g == 0) ? wz : ((g == 1) ? wr : wq);
        g_wQ[i] = pk2(w[o * C_ + 2 * cp], w[o * C_ + 2 * cp + 1]);
    }
    if (i < 3 * C_) {
        int g = i >> 7, c = i & 127;
        const float* wp = (g == 0) ? wzp : ((g == 1) ? wrp : wqp);
        const float* bp = (g == 0) ? bzp : ((g == 1) ? brp : bqp);
        g_wp4[i] = make_float4(wp[3 * c], wp[3 * c + 1], wp[3 * c + 2], bp[c]);
    }
}

// ---------------------------------------------------------------------------
// Transpose: g_hx[b][n][c] = (c<64 ? h[b][c][n] : x[b][c-64][n])
// ---------------------------------------------------------------------------
__global__ __launch_bounds__(256) void k_tr(const float* __restrict__ h,
                                            const float* __restrict__ x) {
    __shared__ float t[C_][33];
    const int b  = blockIdx.x >> 11;
    const int n0 = (blockIdx.x & 2047) * 32;
    const int tid  = threadIdx.x;
    const int lane = tid & 31;
    const int w    = tid >> 5;

    for (int r = w; r < C_; r += 8) {
        const float* src = (r < HID_)
            ? (h + ((size_t)(b * HID_ + r)) * N_)
            : (x + ((size_t)(b * HID_ + (r - HID_))) * N_);
        t[r][lane] = src[n0 + lane];
    }
    __syncthreads();

    const int nn = tid >> 3;
    const int q0 = tid & 7;
    float* dst = g_hx + ((size_t)(b * N_ + n0 + nn)) * C_;
#pragma unroll
    for (int k = 0; k < 4; k++) {
        int c = 4 * (q0 + 8 * k);
        float4 v = make_float4(t[c][nn], t[c + 1][nn], t[c + 2][nn], t[c + 3][nn]);
        *(float4*)(dst + c) = v;
    }
}

// ---------------------------------------------------------------------------
// ZR kernel: 32 points/block, 256 threads.
// ---------------------------------------------------------------------------
__global__ __launch_bounds__(256, 4) void k_zr(
    const float* __restrict__ xyz, const int* __restrict__ knn,
    const float* __restrict__ bzo, const float* __restrict__ bro) {
    __shared__ __align__(16) float aggT[2][NPB][AP];
    __shared__ float  hsm[NPB][65];
    __shared__ float4 srel4[NPB][4];
    __shared__ int    sidx[NPB][4];

    const int b   = blockIdx.x >> 11;
    const int n0  = (blockIdx.x & 2047) * NPB;
    const int tid = threadIdx.x;
    const int lane = tid & 31;
    const int w    = tid >> 5;

    // Stage h rows (needed for r*h)
    for (int i = tid; i < NPB * 32; i += 256) {
        int r = i >> 5, c2 = (i & 31) * 2;
        float2 v = *(const float2*)(g_hx + ((size_t)(b * N_ + n0 + r)) * C_ + c2);
        hsm[r][c2] = v.x; hsm[r][c2 + 1] = v.y;
    }
    if (tid < NPB * 4) {
        int pt = tid >> 2, j = tid & 3;
        int n  = n0 + pt;
        int m  = knn[((size_t)b * N_ + n) * 4 + j];
        sidx[pt][j] = m;
        const float* xb = xyz + (size_t)b * 3 * N_;
        srel4[pt][j] = make_float4(xb[m] - xb[n],
                                   xb[N_ + m] - xb[N_ + n],
                                   xb[2 * N_ + m] - xb[2 * N_ + n], 0.f);
    }
    __syncthreads();

    // Phase 1: gather + shared moments -> both gates' depthwise agg
    {
        const int half = w & 1;
        const int ptb  = w >> 1;           // 0..3
        const int c0   = half * HID_ + 2 * lane;
        const float4 Wz0 = g_wp4[c0],      Wz1 = g_wp4[c0 + 1];
        const float4 Wr0 = g_wp4[C_ + c0], Wr1 = g_wp4[C_ + c0 + 1];
        const float* hxb = g_hx + (size_t)b * N_ * C_ + c0;
#pragma unroll
        for (int u = 0; u < 8; u++) {
            const int pt = ptb + 4 * u;
            int m[4];
#pragma unroll
            for (int j = 0; j < 4; j++) m[j] = sidx[pt][j];
            float2 gv[4];
#pragma unroll
            for (int j = 0; j < 4; j++)
                gv[j] = *(const float2*)(hxb + (size_t)m[j] * C_);

            float m0a = 0.f, m1a = 0.f, m2a = 0.f, m3a = 0.f;
            float m0b = 0.f, m1b = 0.f, m2b = 0.f, m3b = 0.f;
#pragma unroll
            for (int j = 0; j < 4; j++) {
                float4 R = srel4[pt][j];
                float ga = gv[j].x, gb = gv[j].y;
                m0a += ga; m1a = fmaf(R.x, ga, m1a);
                m2a = fmaf(R.y, ga, m2a); m3a = fmaf(R.z, ga, m3a);
                m0b += gb; m1b = fmaf(R.x, gb, m1b);
                m2b = fmaf(R.y, gb, m2b); m3b = fmaf(R.z, gb, m3b);
            }
            float az0 = fmaf(Wz0.x, m1a, fmaf(Wz0.y, m2a, fmaf(Wz0.z, m3a, Wz0.w * m0a)));
            float az1 = fmaf(Wz1.x, m1b, fmaf(Wz1.y, m2b, fmaf(Wz1.z, m3b, Wz1.w * m0b)));
            float ar0 = fmaf(Wr0.x, m1a, fmaf(Wr0.y, m2a, fmaf(Wr0.z, m3a, Wr0.w * m0a)));
            float ar1 = fmaf(Wr1.x, m1b, fmaf(Wr1.y, m2b, fmaf(Wr1.z, m3b, Wr1.w * m0b)));
            *(float2*)&aggT[0][pt][c0] = make_float2(az0, az1);
            *(float2*)&aggT[1][pt][c0] = make_float2(ar0, ar1);
        }
    }
    __syncthreads();

    // Phase 2: matvec, channel-pair packed. warp = (gate, 8-pt group).
    {
        const int g2  = w >> 2;
        const int pt0 = 8 * (w & 3);
        const int o   = lane;
        const u64* wq = g_wQ + g2 * 4096;

        u64 acc[8][2];
#pragma unroll
        for (int k = 0; k < 8; k++) { acc[k][0] = 0ULL; acc[k][1] = 0ULL; }

#pragma unroll 1
        for (int cq = 0; cq < 32; cq++) {      // 4 channels per iter
            u64 Wa0 = wq[(2 * cq) * 64 + o];
            u64 Wb0 = wq[(2 * cq + 1) * 64 + o];
            u64 Wa1 = wq[(2 * cq) * 64 + o + 32];
            u64 Wb1 = wq[(2 * cq + 1) * 64 + o + 32];
#pragma unroll
            for (int k = 0; k < 8; k++) {
                F4 A; A.v = *(const float4*)&aggT[g2][pt0 + k][4 * cq];
                fma2(acc[k][0], A.q[0], Wa0); fma2(acc[k][0], A.q[1], Wb0);
                fma2(acc[k][1], A.q[0], Wa1); fma2(acc[k][1], A.q[1], Wb1);
            }
        }
        const float b0 = (g2 ? bro : bzo)[o];
        const float b1 = (g2 ? bro : bzo)[o + 32];
#pragma unroll
        for (int k = 0; k < 8; k++) {
            const int pt = pt0 + k;
            size_t nb = ((size_t)(b * N_ + n0 + pt)) * HID_;
            float e0, e1, f0, f1;
            up2(acc[k][0], e0, e1);
            up2(acc[k][1], f0, f1);
            float s0 = e0 + e1 + b0;
            float s1 = f0 + f1 + b1;
            if (g2 == 0) {
                g_z[nb + o]      = sigm(s0);
                g_z[nb + o + 32] = sigm(s1);
            } else {
                g_rh[nb + o]      = sigm(s0) * hsm[pt][o];
                g_rh[nb + o + 32] = sigm(s1) * hsm[pt][o + 32];
            }
        }
    }
}

// ---------------------------------------------------------------------------
// Q kernel: 32 points/block, 256 threads. Gathers r*h || x, q gate, combine.
// ---------------------------------------------------------------------------
__global__ __launch_bounds__(256, 4) void k_q(
    const float* __restrict__ xyz, const int* __restrict__ knn,
    const float* __restrict__ bqo, float* __restrict__ out) {
    __shared__ __align__(16) float aggT[NPB][AP];
    __shared__ float  hsm[NPB][65];
    __shared__ float  zsm[NPB][65];
    __shared__ float  osm[NPB][65];
    __shared__ float4 srel4[NPB][4];
    __shared__ int    sidx[NPB][4];

    const int b   = blockIdx.x >> 11;
    const int n0  = (blockIdx.x & 2047) * NPB;
    const int tid = threadIdx.x;
    const int lane = tid & 31;
    const int w    = tid >> 5;

    for (int i = tid; i < NPB * 32; i += 256) {
        int r = i >> 5, c2 = (i & 31) * 2;
        size_t nb = (size_t)(b * N_ + n0 + r);
        float2 vh = *(const float2*)(g_hx + nb * C_ + c2);
        hsm[r][c2] = vh.x; hsm[r][c2 + 1] = vh.y;
        float2 vz = *(const float2*)(g_z + nb * HID_ + c2);
        zsm[r][c2] = vz.x; zsm[r][c2 + 1] = vz.y;
    }
    if (tid < NPB * 4) {
        int pt = tid >> 2, j = tid & 3;
        int n  = n0 + pt;
        int m  = knn[((size_t)b * N_ + n) * 4 + j];
        sidx[pt][j] = m;
        const float* xb = xyz + (size_t)b * 3 * N_;
        srel4[pt][j] = make_float4(xb[m] - xb[n],
                                   xb[N_ + m] - xb[N_ + n],
                                   xb[2 * N_ + m] - xb[2 * N_ + n], 0.f);
    }
    __syncthreads();

    // Phase 1: gather r*h (half 0) or x (half 1) + depthwise agg
    {
        const int half = w & 1;
        const int ptb  = w >> 1;
        const int c0   = half * HID_ + 2 * lane;
        const float4 W0 = g_wp4[2 * C_ + c0], W1 = g_wp4[2 * C_ + c0 + 1];
        const float* gbase = half
            ? (g_hx + (size_t)b * N_ * C_ + HID_ + 2 * lane)
            : (g_rh + (size_t)b * N_ * HID_ + 2 * lane);
        const int stride = half ? C_ : HID_;
#pragma unroll
        for (int u = 0; u < 8; u++) {
            const int pt = ptb + 4 * u;
            int m[4];
#pragma unroll
            for (int j = 0; j < 4; j++) m[j] = sidx[pt][j];
            float2 gv[4];
#pragma unroll
            for (int j = 0; j < 4; j++)
                gv[j] = *(const float2*)(gbase + (size_t)m[j] * stride);

            float m0a = 0.f, m1a = 0.f, m2a = 0.f, m3a = 0.f;
            float m0b = 0.f, m1b = 0.f, m2b = 0.f, m3b = 0.f;
#pragma unroll
            for (int j = 0; j < 4; j++) {
                float4 R = srel4[pt][j];
                float ga = gv[j].x, gb = gv[j].y;
                m0a += ga; m1a = fmaf(R.x, ga, m1a);
                m2a = fmaf(R.y, ga, m2a); m3a = fmaf(R.z, ga, m3a);
                m0b += gb; m1b = fmaf(R.x, gb, m1b);
                m2b = fmaf(R.y, gb, m2b); m3b = fmaf(R.z, gb, m3b);
            }
            float a0 = fmaf(W0.x, m1a, fmaf(W0.y, m2a, fmaf(W0.z, m3a, W0.w * m0a)));
            float a1 = fmaf(W1.x, m1b, fmaf(W1.y, m2b, fmaf(W1.z, m3b, W1.w * m0b)));
            *(float2*)&aggT[pt][c0] = make_float2(a0, a1);
        }
    }
    __syncthreads();

    // Phase 2: matvec (warps 0-3, 8 pts each) + tanh + GRU combine -> osm
    if (w < 4) {
        const int pt0 = 8 * w;
        const int o   = lane;
        const u64* wq = g_wQ + 2 * 4096;

        u64 acc[8][2];
#pragma unroll
        for (int k = 0; k < 8; k++) { acc[k][0] = 0ULL; acc[k][1] = 0ULL; }

#pragma unroll 1
        for (int cq = 0; cq < 32; cq++) {
            u64 Wa0 = wq[(2 * cq) * 64 + o];
            u64 Wb0 = wq[(2 * cq + 1) * 64 + o];
            u64 Wa1 = wq[(2 * cq) * 64 + o + 32];
            u64 Wb1 = wq[(2 * cq + 1) * 64 + o + 32];
#pragma unroll
            for (int k = 0; k < 8; k++) {
                F4 A; A.v = *(const float4*)&aggT[pt0 + k][4 * cq];
                fma2(acc[k][0], A.q[0], Wa0); fma2(acc[k][0], A.q[1], Wb0);
                fma2(acc[k][1], A.q[0], Wa1); fma2(acc[k][1], A.q[1], Wb1);
            }
        }
        const float b0 = bqo[o], b1 = bqo[o + 32];
#pragma unroll
        for (int k = 0; k < 8; k++) {
            const int pt = pt0 + k;
            float e0, e1, f0, f1;
            up2(acc[k][0], e0, e1);
            up2(acc[k][1], f0, f1);
            float q0v = tanhf(e0 + e1 + b0);
            float q1v = tanhf(f0 + f1 + b1);
            float z0 = zsm[pt][o],      h0 = hsm[pt][o];
            float z1 = zsm[pt][o + 32], h1 = hsm[pt][o + 32];
            osm[pt][o]      = fmaf(z0, q0v - h0, h0);
            osm[pt][o + 32] = fmaf(z1, q1v - h1, h1);
        }
    }
    __syncthreads();

    // Phase 3: coalesced transposed output out[b][o][n0..n0+31]
    {
        const int o = tid >> 2;
        const int q = tid & 3;
#pragma unroll
        for (int rep = 0; rep < 2; rep++) {
            int nb = 8 * q + 4 * rep;
            float4 v = make_float4(osm[nb][o], osm[nb + 1][o],
                                   osm[nb + 2][o], osm[nb + 3][o]);
            *(float4*)(out + ((size_t)(b * HID_ + o)) * N_ + n0 + nb) = v;
        }
    }
}

// ---------------------------------------------------------------------------
extern "C" void kernel_launch(void* const* d_in, const int* in_sizes, int n_in,
                              void* d_out, int out_size) {
    const float* xyz = (const float*)d_in[0];
    const float* h   = (const float*)d_in[1];
    const float* x   = (const float*)d_in[2];
    const int*   knn = (const int*)  d_in[3];
    const float* wzp = (const float*)d_in[4];
    const float* bzp = (const float*)d_in[5];
    const float* wzo = (const float*)d_in[6];
    const float* bzo = (const float*)d_in[7];
    const float* wrp = (const float*)d_in[8];
    const float* brp = (const float*)d_in[9];
    const float* wro = (const float*)d_in[10];
    const float* bro = (const float*)d_in[11];
    const float* wqp = (const float*)d_in[12];
    const float* bqp = (const float*)d_in[13];
    const float* wqo = (const float*)d_in[14];
    const float* bqo = (const float*)d_in[15];
    float* out = (float*)d_out;

    k_wT<<<48, 256>>>(wzo, wro, wqo, wzp, bzp, wrp, brp, wqp, bqp);
    k_tr<<<(B_ * N_) / 32, 256>>>(h, x);
    k_zr<<<(B_ * N_) / NPB, 256>>>(xyz, knn, bzo, bro);
    k_q <<<(B_ * N_) / NPB, 256>>>(xyz, knn, bqo, out);
}

// round 5
// speedup vs baseline: 1.5353x; 1.0741x over previous
#include <cuda_runtime.h>
#include <cstdint>
#include <math.h>

#define B_    2
#define N_    65536
#define HID_  64
#define C_    128
#define NPB   32
#define AP    132     // aggT row pad in floats (16B-aligned rows)

typedef unsigned long long u64;

// Scratch (static device globals)
__device__ float  g_hx[(size_t)B_ * N_ * C_];    // [b][n][c] c<64: h, c>=64: x
__device__ float  g_rh[(size_t)B_ * N_ * HID_];  // [b][n][o] r*h
__device__ float  g_z [(size_t)B_ * N_ * HID_];  // [b][n][o] sigmoid(z)
__device__ u64    g_wQ [3 * 64 * 64];            // [g][cp][o] = (w[2cp][o], w[2cp+1][o])
__device__ float4 g_wp4[3 * C_];                 // [g][c] = (w0,w1,w2,bias)

union F4 { float4 v; u64 q[2]; float f[4]; };

__device__ __forceinline__ u64 pk2(float a, float b) {
    u64 r; asm("mov.b64 %0, {%1,%2};" : "=l"(r) : "f"(a), "f"(b)); return r;
}
__device__ __forceinline__ void up2(u64 v, float& a, float& b) {
    asm("mov.b64 {%0,%1}, %2;" : "=f"(a), "=f"(b) : "l"(v));
}
__device__ __forceinline__ void fma2(u64& d, u64 a, u64 b) {
    asm("fma.rn.f32x2 %0, %1, %2, %0;" : "+l"(d) : "l"(a), "l"(b));
}
__device__ __forceinline__ float sigm(float v) { return 1.0f / (1.0f + __expf(-v)); }

// ---------------------------------------------------------------------------
// Weight prep
// ---------------------------------------------------------------------------
__global__ void k_wT(const float* __restrict__ wz, const float* __restrict__ wr,
                     const float* __restrict__ wq,
                     const float* __restrict__ wzp, const float* __restrict__ bzp,
                     const float* __restrict__ wrp, const float* __restrict__ brp,
                     const float* __restrict__ wqp, const float* __restrict__ bqp) {
    int i = blockIdx.x * blockDim.x + threadIdx.x;
    if (i < 3 * 64 * 64) {
        int g  = i >> 12;
        int r  = i & 4095;
        int cp = r >> 6;
        int o  = r & 63;
        const float* w = (g == 0) ? wz : ((g == 1) ? wr : wq);
        g_wQ[i] = pk2(w[o * C_ + 2 * cp], w[o * C_ + 2 * cp + 1]);
    }
    if (i < 3 * C_) {
        int g = i >> 7, c = i & 127;
        const float* wp = (g == 0) ? wzp : ((g == 1) ? wrp : wqp);
        const float* bp = (g == 0) ? bzp : ((g == 1) ? brp : bqp);
        g_wp4[i] = make_float4(wp[3 * c], wp[3 * c + 1], wp[3 * c + 2], bp[c]);
    }
}

// ---------------------------------------------------------------------------
// Transpose: g_hx[b][n][c] = (c<64 ? h[b][c][n] : x[b][c-64][n])
// ---------------------------------------------------------------------------
__global__ __launch_bounds__(256) void k_tr(const float* __restrict__ h,
                                            const float* __restrict__ x) {
    __shared__ float t[C_][33];
    const int b  = blockIdx.x >> 11;
    const int n0 = (blockIdx.x & 2047) * 32;
    const int tid  = threadIdx.x;
    const int lane = tid & 31;
    const int w    = tid >> 5;

    for (int r = w; r < C_; r += 8) {
        const float* src = (r < HID_)
            ? (h + ((size_t)(b * HID_ + r)) * N_)
            : (x + ((size_t)(b * HID_ + (r - HID_))) * N_);
        t[r][lane] = src[n0 + lane];
    }
    __syncthreads();

    const int nn = tid >> 3;
    const int q0 = tid & 7;
    float* dst = g_hx + ((size_t)(b * N_ + n0 + nn)) * C_;
#pragma unroll
    for (int k = 0; k < 4; k++) {
        int c = 4 * (q0 + 8 * k);
        float4 v = make_float4(t[c][nn], t[c + 1][nn], t[c + 2][nn], t[c + 3][nn]);
        *(float4*)(dst + c) = v;
    }
}

// ---------------------------------------------------------------------------
// ZR kernel: 32 points/block, 256 threads.
// ---------------------------------------------------------------------------
__global__ __launch_bounds__(256, 4) void k_zr(
    const float* __restrict__ xyz, const int* __restrict__ knn,
    const float* __restrict__ bzo, const float* __restrict__ bro) {
    __shared__ __align__(16) float aggT[2][NPB][AP];
    __shared__ float4 srel4[NPB][4];
    __shared__ int    sidx[NPB][4];

    const int b   = blockIdx.x >> 11;
    const int n0  = (blockIdx.x & 2047) * NPB;
    const int tid = threadIdx.x;
    const int lane = tid & 31;
    const int w    = tid >> 5;

    if (tid < NPB * 4) {
        int pt = tid >> 2, j = tid & 3;
        int n  = n0 + pt;
        int m  = knn[((size_t)b * N_ + n) * 4 + j];
        sidx[pt][j] = m;
        const float* xb = xyz + (size_t)b * 3 * N_;
        srel4[pt][j] = make_float4(xb[m] - xb[n],
                                   xb[N_ + m] - xb[N_ + n],
                                   xb[2 * N_ + m] - xb[2 * N_ + n], 0.f);
    }
    __syncthreads();

    // Phase 1: gather + shared moments -> both gates' depthwise agg
    {
        const int half = w & 1;
        const int ptb  = w >> 1;           // 0..3
        const int c0   = half * HID_ + 2 * lane;
        const float4 Wz0 = g_wp4[c0],      Wz1 = g_wp4[c0 + 1];
        const float4 Wr0 = g_wp4[C_ + c0], Wr1 = g_wp4[C_ + c0 + 1];
        const float* hxb = g_hx + (size_t)b * N_ * C_ + c0;
#pragma unroll
        for (int u = 0; u < 8; u++) {
            const int pt = ptb + 4 * u;
            int m[4];
#pragma unroll
            for (int j = 0; j < 4; j++) m[j] = sidx[pt][j];
            float2 gv[4];
#pragma unroll
            for (int j = 0; j < 4; j++)
                gv[j] = *(const float2*)(hxb + (size_t)m[j] * C_);

            float m0a = 0.f, m1a = 0.f, m2a = 0.f, m3a = 0.f;
            float m0b = 0.f, m1b = 0.f, m2b = 0.f, m3b = 0.f;
#pragma unroll
            for (int j = 0; j < 4; j++) {
                float4 R = srel4[pt][j];
                float ga = gv[j].x, gb = gv[j].y;
                m0a += ga; m1a = fmaf(R.x, ga, m1a);
                m2a = fmaf(R.y, ga, m2a); m3a = fmaf(R.z, ga, m3a);
                m0b += gb; m1b = fmaf(R.x, gb, m1b);
                m2b = fmaf(R.y, gb, m2b); m3b = fmaf(R.z, gb, m3b);
            }
            float az0 = fmaf(Wz0.x, m1a, fmaf(Wz0.y, m2a, fmaf(Wz0.z, m3a, Wz0.w * m0a)));
            float az1 = fmaf(Wz1.x, m1b, fmaf(Wz1.y, m2b, fmaf(Wz1.z, m3b, Wz1.w * m0b)));
            float ar0 = fmaf(Wr0.x, m1a, fmaf(Wr0.y, m2a, fmaf(Wr0.z, m3a, Wr0.w * m0a)));
            float ar1 = fmaf(Wr1.x, m1b, fmaf(Wr1.y, m2b, fmaf(Wr1.z, m3b, Wr1.w * m0b)));
            *(float2*)&aggT[0][pt][c0] = make_float2(az0, az1);
            *(float2*)&aggT[1][pt][c0] = make_float2(ar0, ar1);
        }
    }
    __syncthreads();

    // Phase 2: matvec, channel-pair packed. warp = (gate, 8-pt group).
    {
        const int g2  = w >> 2;
        const int pt0 = 8 * (w & 3);
        const int o   = lane;
        const u64* wq = g_wQ + g2 * 4096;

        u64 acc[8][2];
#pragma unroll
        for (int k = 0; k < 8; k++) { acc[k][0] = 0ULL; acc[k][1] = 0ULL; }

#pragma unroll 1
        for (int cq = 0; cq < 32; cq++) {      // 4 channels per iter
            u64 Wa0 = wq[(2 * cq) * 64 + o];
            u64 Wb0 = wq[(2 * cq + 1) * 64 + o];
            u64 Wa1 = wq[(2 * cq) * 64 + o + 32];
            u64 Wb1 = wq[(2 * cq + 1) * 64 + o + 32];
#pragma unroll
            for (int k = 0; k < 8; k++) {
                F4 A; A.v = *(const float4*)&aggT[g2][pt0 + k][4 * cq];
                fma2(acc[k][0], A.q[0], Wa0); fma2(acc[k][0], A.q[1], Wb0);
                fma2(acc[k][1], A.q[0], Wa1); fma2(acc[k][1], A.q[1], Wb1);
            }
        }
        const float b0 = (g2 ? bro : bzo)[o];
        const float b1 = (g2 ? bro : bzo)[o + 32];
#pragma unroll
        for (int k = 0; k < 8; k++) {
            const int pt = pt0 + k;
            size_t nb = ((size_t)(b * N_ + n0 + pt)) * HID_;
            float e0, e1, f0, f1;
            up2(acc[k][0], e0, e1);
            up2(acc[k][1], f0, f1);
            float s0 = e0 + e1 + b0;
            float s1 = f0 + f1 + b1;
            if (g2 == 0) {
                g_z[nb + o]      = sigm(s0);
                g_z[nb + o + 32] = sigm(s1);
            } else {
                // coalesced h loads straight from g_hx (lanes contiguous)
                float h0 = g_hx[((size_t)(b * N_ + n0 + pt)) * C_ + o];
                float h1 = g_hx[((size_t)(b * N_ + n0 + pt)) * C_ + o + 32];
                g_rh[nb + o]      = sigm(s0) * h0;
                g_rh[nb + o + 32] = sigm(s1) * h1;
            }
        }
    }
}

// ---------------------------------------------------------------------------
// Q kernel: 32 points/block, 256 threads. Gathers r*h || x, q gate, combine.
// ---------------------------------------------------------------------------
__global__ __launch_bounds__(256, 5) void k_q(
    const float* __restrict__ xyz, const int* __restrict__ knn,
    const float* __restrict__ bqo, float* __restrict__ out) {
    __shared__ __align__(16) float aggT[NPB][AP];
    __shared__ float  osm[NPB][65];
    __shared__ float4 srel4[NPB][4];
    __shared__ int    sidx[NPB][4];

    const int b   = blockIdx.x >> 11;
    const int n0  = (blockIdx.x & 2047) * NPB;
    const int tid = threadIdx.x;
    const int lane = tid & 31;
    const int w    = tid >> 5;

    if (tid < NPB * 4) {
        int pt = tid >> 2, j = tid & 3;
        int n  = n0 + pt;
        int m  = knn[((size_t)b * N_ + n) * 4 + j];
        sidx[pt][j] = m;
        const float* xb = xyz + (size_t)b * 3 * N_;
        srel4[pt][j] = make_float4(xb[m] - xb[n],
                                   xb[N_ + m] - xb[N_ + n],
                                   xb[2 * N_ + m] - xb[2 * N_ + n], 0.f);
    }
    __syncthreads();

    // Phase 1: gather r*h (half 0) or x (half 1) + depthwise agg
    {
        const int half = w & 1;
        const int ptb  = w >> 1;
        const int c0   = half * HID_ + 2 * lane;
        const float4 W0 = g_wp4[2 * C_ + c0], W1 = g_wp4[2 * C_ + c0 + 1];
        const float* gbase = half
            ? (g_hx + (size_t)b * N_ * C_ + HID_ + 2 * lane)
            : (g_rh + (size_t)b * N_ * HID_ + 2 * lane);
        const int stride = half ? C_ : HID_;
#pragma unroll
        for (int u = 0; u < 8; u++) {
            const int pt = ptb + 4 * u;
            int m[4];
#pragma unroll
            for (int j = 0; j < 4; j++) m[j] = sidx[pt][j];
            float2 gv[4];
#pragma unroll
            for (int j = 0; j < 4; j++)
                gv[j] = *(const float2*)(gbase + (size_t)m[j] * stride);

            float m0a = 0.f, m1a = 0.f, m2a = 0.f, m3a = 0.f;
            float m0b = 0.f, m1b = 0.f, m2b = 0.f, m3b = 0.f;
#pragma unroll
            for (int j = 0; j < 4; j++) {
                float4 R = srel4[pt][j];
                float ga = gv[j].x, gb = gv[j].y;
                m0a += ga; m1a = fmaf(R.x, ga, m1a);
                m2a = fmaf(R.y, ga, m2a); m3a = fmaf(R.z, ga, m3a);
                m0b += gb; m1b = fmaf(R.x, gb, m1b);
                m2b = fmaf(R.y, gb, m2b); m3b = fmaf(R.z, gb, m3b);
            }
            float a0 = fmaf(W0.x, m1a, fmaf(W0.y, m2a, fmaf(W0.z, m3a, W0.w * m0a)));
            float a1 = fmaf(W1.x, m1b, fmaf(W1.y, m2b, fmaf(W1.z, m3b, W1.w * m0b)));
            *(float2*)&aggT[pt][c0] = make_float2(a0, a1);
        }
    }
    __syncthreads();

    // Phase 2: matvec — ALL 8 warps, 4 pts each — + tanh + GRU combine -> osm
    {
        const int pt0 = 4 * w;
        const int o   = lane;
        const u64* wq = g_wQ + 2 * 4096;

        u64 acc[4][2];
#pragma unroll
        for (int k = 0; k < 4; k++) { acc[k][0] = 0ULL; acc[k][1] = 0ULL; }

#pragma unroll 1
        for (int cq = 0; cq < 32; cq++) {
            u64 Wa0 = wq[(2 * cq) * 64 + o];
            u64 Wb0 = wq[(2 * cq + 1) * 64 + o];
            u64 Wa1 = wq[(2 * cq) * 64 + o + 32];
            u64 Wb1 = wq[(2 * cq + 1) * 64 + o + 32];
#pragma unroll
            for (int k = 0; k < 4; k++) {
                F4 A; A.v = *(const float4*)&aggT[pt0 + k][4 * cq];
                fma2(acc[k][0], A.q[0], Wa0); fma2(acc[k][0], A.q[1], Wb0);
                fma2(acc[k][1], A.q[0], Wa1); fma2(acc[k][1], A.q[1], Wb1);
            }
        }
        const float b0 = bqo[o], b1 = bqo[o + 32];
#pragma unroll
        for (int k = 0; k < 4; k++) {
            const int pt = pt0 + k;
            size_t nb = (size_t)(b * N_ + n0 + pt);
            float e0, e1, f0, f1;
            up2(acc[k][0], e0, e1);
            up2(acc[k][1], f0, f1);
            float q0v = tanhf(e0 + e1 + b0);
            float q1v = tanhf(f0 + f1 + b1);
            // coalesced direct global loads (lanes contiguous)
            float z0 = g_z [nb * HID_ + o];
            float z1 = g_z [nb * HID_ + o + 32];
            float h0 = g_hx[nb * C_ + o];
            float h1 = g_hx[nb * C_ + o + 32];
            osm[pt][o]      = fmaf(z0, q0v - h0, h0);
            osm[pt][o + 32] = fmaf(z1, q1v - h1, h1);
        }
    }
    __syncthreads();

    // Phase 3: coalesced transposed output out[b][o][n0..n0+31]
    {
        const int o = tid >> 2;
        const int q = tid & 3;
#pragma unroll
        for (int rep = 0; rep < 2; rep++) {
            int nb = 8 * q + 4 * rep;
            float4 v = make_float4(osm[nb][o], osm[nb + 1][o],
                                   osm[nb + 2][o], osm[nb + 3][o]);
            *(float4*)(out + ((size_t)(b * HID_ + o)) * N_ + n0 + nb) = v;
        }
    }
}

// ---------------------------------------------------------------------------
extern "C" void kernel_launch(void* const* d_in, const int* in_sizes, int n_in,
                              void* d_out, int out_size) {
    const float* xyz = (const float*)d_in[0];
    const float* h   = (const float*)d_in[1];
    const float* x   = (const float*)d_in[2];
    const int*   knn = (const int*)  d_in[3];
    const float* wzp = (const float*)d_in[4];
    const float* bzp = (const float*)d_in[5];
    const float* wzo = (const float*)d_in[6];
    const float* bzo = (const float*)d_in[7];
    const float* wrp = (const float*)d_in[8];
    const float* brp = (const float*)d_in[9];
    const float* wro = (const float*)d_in[10];
    const float* bro = (const float*)d_in[11];
    const float* wqp = (const float*)d_in[12];
    const float* bqp = (const float*)d_in[13];
    const float* wqo = (const float*)d_in[14];
    const float* bqo = (const float*)d_in[15];
    float* out = (float*)d_out;

    k_wT<<<48, 256>>>(wzo, wro, wqo, wzp, bzp, wrp, brp, wqp, bqp);
    k_tr<<<(B_ * N_) / 32, 256>>>(h, x);
    k_zr<<<(B_ * N_) / NPB, 256>>>(xyz, knn, bzo, bro);
    k_q <<<(B_ * N_) / NPB, 256>>>(xyz, knn, bqo, out);
}

// round 9
// speedup vs baseline: 2.1327x; 1.3891x over previous
#include <cuda_runtime.h>
#include <cstdint>
#include <math.h>

#define B_    2
#define N_    65536
#define HID_  64
#define C_    128
#define NPB   32
#define AP    132     // aggT row pad in floats

typedef unsigned int u32;

// Scratch (static device globals)
__device__ float  g_hx[(size_t)B_ * N_ * C_];    // [b][n][c] c<64: h, c>=64: x
__device__ float  g_rh[(size_t)B_ * N_ * HID_];  // [b][n][o] r*h
__device__ float  g_z [(size_t)B_ * N_ * HID_];  // [b][n][o] sigmoid(z)
__device__ float4 g_wF[3 * 4 * 16 * 32];         // [gate][mt][kt][lane] A-fragments (tf32)
__device__ float4 g_wp4[3 * C_];                 // [g][c] = (w0,w1,w2,bias)

__device__ __forceinline__ float sigm(float v) { return 1.0f / (1.0f + __expf(-v)); }

__device__ __forceinline__ float tf32r(float v) {
    u32 r; asm("cvt.rna.tf32.f32 %0, %1;" : "=r"(r) : "f"(v));
    return __uint_as_float(r);
}

__device__ __forceinline__ void mma_tf32(float4& d, u32 a0, u32 a1, u32 a2, u32 a3,
                                         u32 b0, u32 b1) {
    asm volatile(
        "mma.sync.aligned.m16n8k8.row.col.f32.tf32.tf32.f32 "
        "{%0,%1,%2,%3}, {%4,%5,%6,%7}, {%8,%9}, {%0,%1,%2,%3};"
        : "+f"(d.x), "+f"(d.y), "+f"(d.z), "+f"(d.w)
        : "r"(a0), "r"(a1), "r"(a2), "r"(a3), "r"(b0), "r"(b1));
}

// ---------------------------------------------------------------------------
// Weight prep: A-fragments (tf32) for mma + packed position weights
// ---------------------------------------------------------------------------
__global__ void k_wT(const float* __restrict__ wz, const float* __restrict__ wr,
                     const float* __restrict__ wq,
                     const float* __restrict__ wzp, const float* __restrict__ bzp,
                     const float* __restrict__ wrp, const float* __restrict__ brp,
                     const float* __restrict__ wqp, const float* __restrict__ bqp) {
    int i = blockIdx.x * blockDim.x + threadIdx.x;
    if (i < 3 * 4 * 16 * 32) {
        int gate = i >> 11;
        int r    = i & 2047;
        int mt   = r >> 9;
        int r2   = r & 511;
        int kt   = r2 >> 5;
        int lane = r2 & 31;
        int g = lane >> 2, t = lane & 3;
        int o = 16 * mt + g, c = 8 * kt + t;
        const float* w = (gate == 0) ? wz : ((gate == 1) ? wr : wq);
        float4 f;
        f.x = tf32r(w[o * C_ + c]);            // a0: (o,   c)
        f.y = tf32r(w[(o + 8) * C_ + c]);      // a1: (o+8, c)
        f.z = tf32r(w[o * C_ + c + 4]);        // a2: (o,   c+4)
        f.w = tf32r(w[(o + 8) * C_ + c + 4]);  // a3: (o+8, c+4)
        g_wF[i] = f;
    }
    if (i < 3 * C_) {
        int g = i >> 7, c = i & 127;
        const float* wp = (g == 0) ? wzp : ((g == 1) ? wrp : wqp);
        const float* bp = (g == 0) ? bzp : ((g == 1) ? brp : bqp);
        g_wp4[i] = make_float4(wp[3 * c], wp[3 * c + 1], wp[3 * c + 2], bp[c]);
    }
}

// ---------------------------------------------------------------------------
// Transpose: g_hx[b][n][c] = (c<64 ? h[b][c][n] : x[b][c-64][n])
// ---------------------------------------------------------------------------
__global__ __launch_bounds__(256) void k_tr(const float* __restrict__ h,
                                            const float* __restrict__ x) {
    __shared__ float t[C_][33];
    const int b  = blockIdx.x >> 11;
    const int n0 = (blockIdx.x & 2047) * 32;
    const int tid  = threadIdx.x;
    const int lane = tid & 31;
    const int w    = tid >> 5;

    for (int r = w; r < C_; r += 8) {
        const float* src = (r < HID_)
            ? (h + ((size_t)(b * HID_ + r)) * N_)
            : (x + ((size_t)(b * HID_ + (r - HID_))) * N_);
        t[r][lane] = src[n0 + lane];
    }
    __syncthreads();

    const int nn = tid >> 3;
    const int q0 = tid & 7;
    float* dst = g_hx + ((size_t)(b * N_ + n0 + nn)) * C_;
#pragma unroll
    for (int k = 0; k < 4; k++) {
        int c = 4 * (q0 + 8 * k);
        float4 v = make_float4(t[c][nn], t[c + 1][nn], t[c + 2][nn], t[c + 3][nn]);
        *(float4*)(dst + c) = v;
    }
}

// ---------------------------------------------------------------------------
// ZR kernel: 32 points/block, 256 threads.
// Phase 1: gather + moments -> aggT (tf32-rounded)
// Phase 2: tf32 mma matvec (warp = gate x m-tile), sigmoid -> zsm/rsm
// Phase 3: coalesced writes of g_z and g_rh (= r * h)
// ---------------------------------------------------------------------------
__global__ __launch_bounds__(256, 4) void k_zr(
    const float* __restrict__ xyz, const int* __restrict__ knn,
    const float* __restrict__ bzo, const float* __restrict__ bro) {
    __shared__ __align__(16) float aggT[2][NPB][AP];
    __shared__ float  zsm[NPB][65];
    __shared__ float  rsm[NPB][65];
    __shared__ float4 srel4[NPB][4];
    __shared__ int    sidx[NPB][4];

    const int b   = blockIdx.x >> 11;
    const int n0  = (blockIdx.x & 2047) * NPB;
    const int tid = threadIdx.x;
    const int lane = tid & 31;
    const int w    = tid >> 5;

    if (tid < NPB * 4) {
        int pt = tid >> 2, j = tid & 3;
        int n  = n0 + pt;
        int m  = knn[((size_t)b * N_ + n) * 4 + j];
        sidx[pt][j] = m;
        const float* xb = xyz + (size_t)b * 3 * N_;
        srel4[pt][j] = make_float4(xb[m] - xb[n],
                                   xb[N_ + m] - xb[N_ + n],
                                   xb[2 * N_ + m] - xb[2 * N_ + n], 0.f);
    }
    __syncthreads();

    // Phase 1: gather + shared moments -> both gates' depthwise agg
    {
        const int half = w & 1;
        const int ptb  = w >> 1;           // 0..3
        const int c0   = half * HID_ + 2 * lane;
        const float4 Wz0 = g_wp4[c0],      Wz1 = g_wp4[c0 + 1];
        const float4 Wr0 = g_wp4[C_ + c0], Wr1 = g_wp4[C_ + c0 + 1];
        const float* hxb = g_hx + (size_t)b * N_ * C_ + c0;
#pragma unroll
        for (int u = 0; u < 8; u++) {
            const int pt = ptb + 4 * u;
            int m[4];
#pragma unroll
            for (int j = 0; j < 4; j++) m[j] = sidx[pt][j];
            float2 gv[4];
#pragma unroll
            for (int j = 0; j < 4; j++)
                gv[j] = *(const float2*)(hxb + (size_t)m[j] * C_);

            float m0a = 0.f, m1a = 0.f, m2a = 0.f, m3a = 0.f;
            float m0b = 0.f, m1b = 0.f, m2b = 0.f, m3b = 0.f;
#pragma unroll
            for (int j = 0; j < 4; j++) {
                float4 R = srel4[pt][j];
                float ga = gv[j].x, gb = gv[j].y;
                m0a += ga; m1a = fmaf(R.x, ga, m1a);
                m2a = fmaf(R.y, ga, m2a); m3a = fmaf(R.z, ga, m3a);
                m0b += gb; m1b = fmaf(R.x, gb, m1b);
                m2b = fmaf(R.y, gb, m2b); m3b = fmaf(R.z, gb, m3b);
            }
            float az0 = fmaf(Wz0.x, m1a, fmaf(Wz0.y, m2a, fmaf(Wz0.z, m3a, Wz0.w * m0a)));
            float az1 = fmaf(Wz1.x, m1b, fmaf(Wz1.y, m2b, fmaf(Wz1.z, m3b, Wz1.w * m0b)));
            float ar0 = fmaf(Wr0.x, m1a, fmaf(Wr0.y, m2a, fmaf(Wr0.z, m3a, Wr0.w * m0a)));
            float ar1 = fmaf(Wr1.x, m1b, fmaf(Wr1.y, m2b, fmaf(Wr1.z, m3b, Wr1.w * m0b)));
            *(float2*)&aggT[0][pt][c0] = make_float2(tf32r(az0), tf32r(az1));
            *(float2*)&aggT[1][pt][c0] = make_float2(tf32r(ar0), tf32r(ar1));
        }
    }
    __syncthreads();

    // Phase 2: tf32 mma. warp = (gate g2, m-tile mt); loops 4 n-tiles x 16 k-tiles
    {
        const int g2 = w >> 2;
        const int mt = w & 3;
        const int g  = lane >> 2, t = lane & 3;
        const float4* wf = g_wF + ((size_t)(g2 * 4 + mt) * 16) * 32 + lane;

        float4 acc[4];
#pragma unroll
        for (int nt = 0; nt < 4; nt++) acc[nt] = make_float4(0.f, 0.f, 0.f, 0.f);

#pragma unroll 4
        for (int kt = 0; kt < 16; kt++) {
            float4 A = wf[kt * 32];
            u32 a0 = __float_as_uint(A.x), a1 = __float_as_uint(A.y);
            u32 a2 = __float_as_uint(A.z), a3 = __float_as_uint(A.w);
#pragma unroll
            for (int nt = 0; nt < 4; nt++) {
                u32 b0 = __float_as_uint(aggT[g2][8 * nt + g][8 * kt + t]);
                u32 b1 = __float_as_uint(aggT[g2][8 * nt + g][8 * kt + t + 4]);
                mma_tf32(acc[nt], a0, a1, a2, a3, b0, b1);
            }
        }
        const float* bo = g2 ? bro : bzo;
        const float b0v = bo[16 * mt + g];
        const float b1v = bo[16 * mt + g + 8];
        float (*dst)[65] = g2 ? rsm : zsm;
#pragma unroll
        for (int nt = 0; nt < 4; nt++) {
            int pt = 8 * nt + 2 * t;
            int o  = 16 * mt + g;
            dst[pt][o]         = sigm(acc[nt].x + b0v);
            dst[pt + 1][o]     = sigm(acc[nt].y + b0v);
            dst[pt][o + 8]     = sigm(acc[nt].z + b1v);
            dst[pt + 1][o + 8] = sigm(acc[nt].w + b1v);
        }
    }
    __syncthreads();

    // Phase 3: coalesced writes
    for (int i = tid; i < NPB * HID_; i += 256) {
        int pt = i >> 6, o = i & 63;
        size_t nb = (size_t)(b * N_ + n0 + pt);
        g_z[nb * HID_ + o] = zsm[pt][o];
        float hv = g_hx[nb * C_ + o];
        g_rh[nb * HID_ + o] = rsm[pt][o] * hv;
    }
}

// ---------------------------------------------------------------------------
// Q kernel: 32 points/block, 256 threads.
// ---------------------------------------------------------------------------
__global__ __launch_bounds__(256, 5) void k_q(
    const float* __restrict__ xyz, const int* __restrict__ knn,
    const float* __restrict__ bqo, float* __restrict__ out) {
    __shared__ __align__(16) float aggT[NPB][AP];
    __shared__ float  osm[NPB][65];
    __shared__ float4 srel4[NPB][4];
    __shared__ int    sidx[NPB][4];

    const int b   = blockIdx.x >> 11;
    const int n0  = (blockIdx.x & 2047) * NPB;
    const int tid = threadIdx.x;
    const int lane = tid & 31;
    const int w    = tid >> 5;

    if (tid < NPB * 4) {
        int pt = tid >> 2, j = tid & 3;
        int n  = n0 + pt;
        int m  = knn[((size_t)b * N_ + n) * 4 + j];
        sidx[pt][j] = m;
        const float* xb = xyz + (size_t)b * 3 * N_;
        srel4[pt][j] = make_float4(xb[m] - xb[n],
                                   xb[N_ + m] - xb[N_ + n],
                                   xb[2 * N_ + m] - xb[2 * N_ + n], 0.f);
    }
    __syncthreads();

    // Phase 1: gather r*h (half 0) or x (half 1) + depthwise agg
    {
        const int half = w & 1;
        const int ptb  = w >> 1;
        const int c0   = half * HID_ + 2 * lane;
        const float4 W0 = g_wp4[2 * C_ + c0], W1 = g_wp4[2 * C_ + c0 + 1];
        const float* gbase = half
            ? (g_hx + (size_t)b * N_ * C_ + HID_ + 2 * lane)
            : (g_rh + (size_t)b * N_ * HID_ + 2 * lane);
        const int stride = half ? C_ : HID_;
#pragma unroll
        for (int u = 0; u < 8; u++) {
            const int pt = ptb + 4 * u;
            int m[4];
#pragma unroll
            for (int j = 0; j < 4; j++) m[j] = sidx[pt][j];
            float2 gv[4];
#pragma unroll
            for (int j = 0; j < 4; j++)
                gv[j] = *(const float2*)(gbase + (size_t)m[j] * stride);

            float m0a = 0.f, m1a = 0.f, m2a = 0.f, m3a = 0.f;
            float m0b = 0.f, m1b = 0.f, m2b = 0.f, m3b = 0.f;
#pragma unroll
            for (int j = 0; j < 4; j++) {
                float4 R = srel4[pt][j];
                float ga = gv[j].x, gb = gv[j].y;
                m0a += ga; m1a = fmaf(R.x, ga, m1a);
                m2a = fmaf(R.y, ga, m2a); m3a = fmaf(R.z, ga, m3a);
                m0b += gb; m1b = fmaf(R.x, gb, m1b);
                m2b = fmaf(R.y, gb, m2b); m3b = fmaf(R.z, gb, m3b);
            }
            float a0 = fmaf(W0.x, m1a, fmaf(W0.y, m2a, fmaf(W0.z, m3a, W0.w * m0a)));
            float a1 = fmaf(W1.x, m1b, fmaf(W1.y, m2b, fmaf(W1.z, m3b, W1.w * m0b)));
            *(float2*)&aggT[pt][c0] = make_float2(tf32r(a0), tf32r(a1));
        }
    }
    __syncthreads();

    // Phase 2: tf32 mma. warp = (m-tile mt, n-half nh); tanh -> osm
    {
        const int mt = w & 3;
        const int nh = w >> 2;            // 0..1, covers n-tiles {2nh, 2nh+1}
        const int g  = lane >> 2, t = lane & 3;
        const float4* wf = g_wF + ((size_t)(2 * 4 + mt) * 16) * 32 + lane;

        float4 acc[2];
        acc[0] = make_float4(0.f, 0.f, 0.f, 0.f);
        acc[1] = make_float4(0.f, 0.f, 0.f, 0.f);

#pragma unroll 4
        for (int kt = 0; kt < 16; kt++) {
            float4 A = wf[kt * 32];
            u32 a0 = __float_as_uint(A.x), a1 = __float_as_uint(A.y);
            u32 a2 = __float_as_uint(A.z), a3 = __float_as_uint(A.w);
#pragma unroll
            for (int j = 0; j < 2; j++) {
                int nt = 2 * nh + j;
                u32 b0 = __float_as_uint(aggT[8 * nt + g][8 * kt + t]);
                u32 b1 = __float_as_uint(aggT[8 * nt + g][8 * kt + t + 4]);
                mma_tf32(acc[j], a0, a1, a2, a3, b0, b1);
            }
        }
        const float b0v = bqo[16 * mt + g];
        const float b1v = bqo[16 * mt + g + 8];
#pragma unroll
        for (int j = 0; j < 2; j++) {
            int pt = 8 * (2 * nh + j) + 2 * t;
            int o  = 16 * mt + g;
            osm[pt][o]         = tanhf(acc[j].x + b0v);
            osm[pt + 1][o]     = tanhf(acc[j].y + b0v);
            osm[pt][o + 8]     = tanhf(acc[j].z + b1v);
            osm[pt + 1][o + 8] = tanhf(acc[j].w + b1v);
        }
    }
    __syncthreads();

    // GRU combine (coalesced loads), update osm in place
    for (int i = tid; i < NPB * HID_; i += 256) {
        int pt = i >> 6, o = i & 63;
        size_t nb = (size_t)(b * N_ + n0 + pt);
        float z  = g_z [nb * HID_ + o];
        float hv = g_hx[nb * C_ + o];
        float qv = osm[pt][o];
        osm[pt][o] = fmaf(z, qv - hv, hv);
    }
    __syncthreads();

    // Phase 3: coalesced transposed output out[b][o][n0..n0+31]
    {
        const int o = tid >> 2;
        const int q = tid & 3;
#pragma unroll
        for (int rep = 0; rep < 2; rep++) {
            int nb = 8 * q + 4 * rep;
            float4 v = make_float4(osm[nb][o], osm[nb + 1][o],
                                   osm[nb + 2][o], osm[nb + 3][o]);
            *(float4*)(out + ((size_t)(b * HID_ + o)) * N_ + n0 + nb) = v;
        }
    }
}

// ---------------------------------------------------------------------------
extern "C" void kernel_launch(void* const* d_in, const int* in_sizes, int n_in,
                              void* d_out, int out_size) {
    const float* xyz = (const float*)d_in[0];
    const float* h   = (const float*)d_in[1];
    const float* x   = (const float*)d_in[2];
    const int*   knn = (const int*)  d_in[3];
    const float* wzp = (const float*)d_in[4];
    const float* bzp = (const float*)d_in[5];
    const float* wzo = (const float*)d_in[6];
    const float* bzo = (const float*)d_in[7];
    const float* wrp = (const float*)d_in[8];
    const float* brp = (const float*)d_in[9];
    const float* wro = (const float*)d_in[10];
    const float* bro = (const float*)d_in[11];
    const float* wqp = (const float*)d_in[12];
    const float* bqp = (const float*)d_in[13];
    const float* wqo = (const float*)d_in[14];
    const float* bqo = (const float*)d_in[15];
    float* out = (float*)d_out;

    k_wT<<<24, 256>>>(wzo, wro, wqo, wzp, bzp, wrp, brp, wqp, bqp);
    k_tr<<<(B_ * N_) / 32, 256>>>(h, x);
    k_zr<<<(B_ * N_) / NPB, 256>>>(xyz, knn, bzo, bro);
    k_q <<<(B_ * N_) / NPB, 256>>>(xyz, knn, bqo, out);
}

// round 10
// speedup vs baseline: 2.3525x; 1.1030x over previous
#include <cuda_runtime.h>
#include <cstdint>
#include <math.h>

#define B_    2
#define N_    65536
#define HID_  64
#define C_    128
#define NPB   32
#define AP    132     // aggT row pad in floats

typedef unsigned int u32;

// Scratch (static device globals)
__device__ float  g_hx[(size_t)B_ * N_ * C_];    // [b][n][c] c<64: h, c>=64: x
__device__ float  g_rh[(size_t)B_ * N_ * HID_];  // [b][n][o] r*h
__device__ float  g_z [(size_t)B_ * N_ * HID_];  // [b][n][o] sigmoid(z)
__device__ float4 g_wF[3 * 4 * 16 * 32];         // [gate][mt][kt][lane] A-fragments (tf32)
__device__ float4 g_wp4[3 * C_];                 // [g][c] = (w0,w1,w2,bias)

__device__ __forceinline__ float sigm(float v) { return 1.0f / (1.0f + __expf(-v)); }

__device__ __forceinline__ float tf32r(float v) {
    u32 r; asm("cvt.rna.tf32.f32 %0, %1;" : "=r"(r) : "f"(v));
    return __uint_as_float(r);
}

__device__ __forceinline__ void mma_tf32(float4& d, u32 a0, u32 a1, u32 a2, u32 a3,
                                         u32 b0, u32 b1) {
    asm volatile(
        "mma.sync.aligned.m16n8k8.row.col.f32.tf32.tf32.f32 "
        "{%0,%1,%2,%3}, {%4,%5,%6,%7}, {%8,%9}, {%0,%1,%2,%3};"
        : "+f"(d.x), "+f"(d.y), "+f"(d.z), "+f"(d.w)
        : "r"(a0), "r"(a1), "r"(a2), "r"(a3), "r"(b0), "r"(b1));
}

// ---------------------------------------------------------------------------
// Weight prep: A-fragments (tf32) for mma + packed position weights
// ---------------------------------------------------------------------------
__global__ void k_wT(const float* __restrict__ wz, const float* __restrict__ wr,
                     const float* __restrict__ wq,
                     const float* __restrict__ wzp, const float* __restrict__ bzp,
                     const float* __restrict__ wrp, const float* __restrict__ brp,
                     const float* __restrict__ wqp, const float* __restrict__ bqp) {
    int i = blockIdx.x * blockDim.x + threadIdx.x;
    if (i < 3 * 4 * 16 * 32) {
        int gate = i >> 11;
        int r    = i & 2047;
        int mt   = r >> 9;
        int r2   = r & 511;
        int kt   = r2 >> 5;
        int lane = r2 & 31;
        int g = lane >> 2, t = lane & 3;
        int o = 16 * mt + g, c = 8 * kt + t;
        const float* w = (gate == 0) ? wz : ((gate == 1) ? wr : wq);
        float4 f;
        f.x = tf32r(w[o * C_ + c]);
        f.y = tf32r(w[(o + 8) * C_ + c]);
        f.z = tf32r(w[o * C_ + c + 4]);
        f.w = tf32r(w[(o + 8) * C_ + c + 4]);
        g_wF[i] = f;
    }
    if (i < 3 * C_) {
        int g = i >> 7, c = i & 127;
        const float* wp = (g == 0) ? wzp : ((g == 1) ? wrp : wqp);
        const float* bp = (g == 0) ? bzp : ((g == 1) ? brp : bqp);
        g_wp4[i] = make_float4(wp[3 * c], wp[3 * c + 1], wp[3 * c + 2], bp[c]);
    }
}

// ---------------------------------------------------------------------------
// Transpose: g_hx[b][n][c] = (c<64 ? h[b][c][n] : x[b][c-64][n])  64-pt tiles
// ---------------------------------------------------------------------------
__global__ __launch_bounds__(256) void k_tr(const float* __restrict__ h,
                                            const float* __restrict__ x) {
    __shared__ float t[C_][66];
    const int b  = blockIdx.x >> 10;            // N_/64 = 1024 blocks per batch
    const int n0 = (blockIdx.x & 1023) * 64;
    const int tid  = threadIdx.x;
    const int lane = tid & 31;
    const int w    = tid >> 5;

    for (int r = w; r < C_; r += 8) {
        const float* src = (r < HID_)
            ? (h + ((size_t)(b * HID_ + r)) * N_)
            : (x + ((size_t)(b * HID_ + (r - HID_))) * N_);
        t[r][lane]      = src[n0 + lane];
        t[r][lane + 32] = src[n0 + lane + 32];
    }
    __syncthreads();

    const int nn = tid >> 2;          // 64 points, 4 threads per point
    const int q0 = tid & 3;
    float* dst = g_hx + ((size_t)(b * N_ + n0 + nn)) * C_;
#pragma unroll
    for (int k = 0; k < 8; k++) {
        int c = 4 * (q0 + 4 * k);
        float4 v = make_float4(t[c][nn], t[c + 1][nn], t[c + 2][nn], t[c + 3][nn]);
        *(float4*)(dst + c) = v;
    }
}

// ---------------------------------------------------------------------------
// ZR kernel: 32 points/block, 256 threads. zsm/rsm alias aggT storage.
// ---------------------------------------------------------------------------
__global__ __launch_bounds__(256, 5) void k_zr(
    const float* __restrict__ xyz, const int* __restrict__ knn,
    const float* __restrict__ bzo, const float* __restrict__ bro) {
    __shared__ __align__(16) float sbuf[2 * NPB * AP];
    __shared__ float4 srel4[NPB][4];
    __shared__ int    sidx[NPB][4];

    float (*aggT)[NPB][AP] = (float(*)[NPB][AP])sbuf;
    float (*zsm)[65] = (float(*)[65])sbuf;               // alias (post-sync)
    float (*rsm)[65] = (float(*)[65])(sbuf + NPB * 65);

    const int b   = blockIdx.x >> 11;
    const int n0  = (blockIdx.x & 2047) * NPB;
    const int tid = threadIdx.x;
    const int lane = tid & 31;
    const int w    = tid >> 5;

    if (tid < NPB * 4) {
        int pt = tid >> 2, j = tid & 3;
        int n  = n0 + pt;
        int m  = knn[((size_t)b * N_ + n) * 4 + j];
        sidx[pt][j] = m;
        const float* xb = xyz + (size_t)b * 3 * N_;
        srel4[pt][j] = make_float4(xb[m] - xb[n],
                                   xb[N_ + m] - xb[N_ + n],
                                   xb[2 * N_ + m] - xb[2 * N_ + n], 0.f);
    }
    __syncthreads();

    // Phase 1: gather + shared moments -> both gates' depthwise agg
    {
        const int half = w & 1;
        const int ptb  = w >> 1;
        const int c0   = half * HID_ + 2 * lane;
        const float4 Wz0 = g_wp4[c0],      Wz1 = g_wp4[c0 + 1];
        const float4 Wr0 = g_wp4[C_ + c0], Wr1 = g_wp4[C_ + c0 + 1];
        const float* hxb = g_hx + (size_t)b * N_ * C_ + c0;
#pragma unroll
        for (int u = 0; u < 8; u++) {
            const int pt = ptb + 4 * u;
            int m[4];
#pragma unroll
            for (int j = 0; j < 4; j++) m[j] = sidx[pt][j];
            float2 gv[4];
#pragma unroll
            for (int j = 0; j < 4; j++)
                gv[j] = *(const float2*)(hxb + (size_t)m[j] * C_);

            float m0a = 0.f, m1a = 0.f, m2a = 0.f, m3a = 0.f;
            float m0b = 0.f, m1b = 0.f, m2b = 0.f, m3b = 0.f;
#pragma unroll
            for (int j = 0; j < 4; j++) {
                float4 R = srel4[pt][j];
                float ga = gv[j].x, gb = gv[j].y;
                m0a += ga; m1a = fmaf(R.x, ga, m1a);
                m2a = fmaf(R.y, ga, m2a); m3a = fmaf(R.z, ga, m3a);
                m0b += gb; m1b = fmaf(R.x, gb, m1b);
                m2b = fmaf(R.y, gb, m2b); m3b = fmaf(R.z, gb, m3b);
            }
            float az0 = fmaf(Wz0.x, m1a, fmaf(Wz0.y, m2a, fmaf(Wz0.z, m3a, Wz0.w * m0a)));
            float az1 = fmaf(Wz1.x, m1b, fmaf(Wz1.y, m2b, fmaf(Wz1.z, m3b, Wz1.w * m0b)));
            float ar0 = fmaf(Wr0.x, m1a, fmaf(Wr0.y, m2a, fmaf(Wr0.z, m3a, Wr0.w * m0a)));
            float ar1 = fmaf(Wr1.x, m1b, fmaf(Wr1.y, m2b, fmaf(Wr1.z, m3b, Wr1.w * m0b)));
            *(float2*)&aggT[0][pt][c0] = make_float2(tf32r(az0), tf32r(az1));
            *(float2*)&aggT[1][pt][c0] = make_float2(tf32r(ar0), tf32r(ar1));
        }
    }
    __syncthreads();

    // Phase 2: tf32 mma. warp = (gate g2, m-tile mt); 4 n-tiles x 16 k-tiles
    {
        const int g2 = w >> 2;
        const int mt = w & 3;
        const int g  = lane >> 2, t = lane & 3;
        const float4* wf = g_wF + ((size_t)(g2 * 4 + mt) * 16) * 32 + lane;

        float4 acc[4];
#pragma unroll
        for (int nt = 0; nt < 4; nt++) acc[nt] = make_float4(0.f, 0.f, 0.f, 0.f);

#pragma unroll 4
        for (int kt = 0; kt < 16; kt++) {
            float4 A = wf[kt * 32];
            u32 a0 = __float_as_uint(A.x), a1 = __float_as_uint(A.y);
            u32 a2 = __float_as_uint(A.z), a3 = __float_as_uint(A.w);
#pragma unroll
            for (int nt = 0; nt < 4; nt++) {
                u32 b0 = __float_as_uint(aggT[g2][8 * nt + g][8 * kt + t]);
                u32 b1 = __float_as_uint(aggT[g2][8 * nt + g][8 * kt + t + 4]);
                mma_tf32(acc[nt], a0, a1, a2, a3, b0, b1);
            }
        }
        __syncthreads();   // aggT dead; zsm/rsm may now overwrite it

        const float* bo = g2 ? bro : bzo;
        const float b0v = bo[16 * mt + g];
        const float b1v = bo[16 * mt + g + 8];
        float (*dst)[65] = g2 ? rsm : zsm;
#pragma unroll
        for (int nt = 0; nt < 4; nt++) {
            int pt = 8 * nt + 2 * t;
            int o  = 16 * mt + g;
            dst[pt][o]         = sigm(acc[nt].x + b0v);
            dst[pt + 1][o]     = sigm(acc[nt].y + b0v);
            dst[pt][o + 8]     = sigm(acc[nt].z + b1v);
            dst[pt + 1][o + 8] = sigm(acc[nt].w + b1v);
        }
    }
    __syncthreads();

    // Phase 3: coalesced writes
    for (int i = tid; i < NPB * HID_; i += 256) {
        int pt = i >> 6, o = i & 63;
        size_t nb = (size_t)(b * N_ + n0 + pt);
        g_z[nb * HID_ + o] = zsm[pt][o];
        float hv = g_hx[nb * C_ + o];
        g_rh[nb * HID_ + o] = rsm[pt][o] * hv;
    }
}

// ---------------------------------------------------------------------------
// Q kernel: 32 points/block, 256 threads. osm aliases aggT storage.
// ---------------------------------------------------------------------------
__global__ __launch_bounds__(256, 6) void k_q(
    const float* __restrict__ xyz, const int* __restrict__ knn,
    const float* __restrict__ bqo, float* __restrict__ out) {
    __shared__ __align__(16) float sbuf[NPB * AP];
    __shared__ float4 srel4[NPB][4];
    __shared__ int    sidx[NPB][4];

    float (*aggT)[AP] = (float(*)[AP])sbuf;
    float (*osm)[65]  = (float(*)[65])sbuf;   // alias (post-sync)

    const int b   = blockIdx.x >> 11;
    const int n0  = (blockIdx.x & 2047) * NPB;
    const int tid = threadIdx.x;
    const int lane = tid & 31;
    const int w    = tid >> 5;

    if (tid < NPB * 4) {
        int pt = tid >> 2, j = tid & 3;
        int n  = n0 + pt;
        int m  = knn[((size_t)b * N_ + n) * 4 + j];
        sidx[pt][j] = m;
        const float* xb = xyz + (size_t)b * 3 * N_;
        srel4[pt][j] = make_float4(xb[m] - xb[n],
                                   xb[N_ + m] - xb[N_ + n],
                                   xb[2 * N_ + m] - xb[2 * N_ + n], 0.f);
    }
    __syncthreads();

    // Phase 1: gather r*h (half 0) or x (half 1) + depthwise agg
    {
        const int half = w & 1;
        const int ptb  = w >> 1;
        const int c0   = half * HID_ + 2 * lane;
        const float4 W0 = g_wp4[2 * C_ + c0], W1 = g_wp4[2 * C_ + c0 + 1];
        const float* gbase = half
            ? (g_hx + (size_t)b * N_ * C_ + HID_ + 2 * lane)
            : (g_rh + (size_t)b * N_ * HID_ + 2 * lane);
        const int stride = half ? C_ : HID_;
#pragma unroll
        for (int u = 0; u < 8; u++) {
            const int pt = ptb + 4 * u;
            int m[4];
#pragma unroll
            for (int j = 0; j < 4; j++) m[j] = sidx[pt][j];
            float2 gv[4];
#pragma unroll
            for (int j = 0; j < 4; j++)
                gv[j] = *(const float2*)(gbase + (size_t)m[j] * stride);

            float m0a = 0.f, m1a = 0.f, m2a = 0.f, m3a = 0.f;
            float m0b = 0.f, m1b = 0.f, m2b = 0.f, m3b = 0.f;
#pragma unroll
            for (int j = 0; j < 4; j++) {
                float4 R = srel4[pt][j];
                float ga = gv[j].x, gb = gv[j].y;
                m0a += ga; m1a = fmaf(R.x, ga, m1a);
                m2a = fmaf(R.y, ga, m2a); m3a = fmaf(R.z, ga, m3a);
                m0b += gb; m1b = fmaf(R.x, gb, m1b);
                m2b = fmaf(R.y, gb, m2b); m3b = fmaf(R.z, gb, m3b);
            }
            float a0 = fmaf(W0.x, m1a, fmaf(W0.y, m2a, fmaf(W0.z, m3a, W0.w * m0a)));
            float a1 = fmaf(W1.x, m1b, fmaf(W1.y, m2b, fmaf(W1.z, m3b, W1.w * m0b)));
            *(float2*)&aggT[pt][c0] = make_float2(tf32r(a0), tf32r(a1));
        }
    }
    __syncthreads();

    // Phase 2: tf32 mma. warp = (m-tile mt, n-half nh); tanh -> osm (aliased)
    {
        const int mt = w & 3;
        const int nh = w >> 2;
        const int g  = lane >> 2, t = lane & 3;
        const float4* wf = g_wF + ((size_t)(2 * 4 + mt) * 16) * 32 + lane;

        float4 acc[2];
        acc[0] = make_float4(0.f, 0.f, 0.f, 0.f);
        acc[1] = make_float4(0.f, 0.f, 0.f, 0.f);

#pragma unroll 4
        for (int kt = 0; kt < 16; kt++) {
            float4 A = wf[kt * 32];
            u32 a0 = __float_as_uint(A.x), a1 = __float_as_uint(A.y);
            u32 a2 = __float_as_uint(A.z), a3 = __float_as_uint(A.w);
#pragma unroll
            for (int j = 0; j < 2; j++) {
                int nt = 2 * nh + j;
                u32 b0 = __float_as_uint(aggT[8 * nt + g][8 * kt + t]);
                u32 b1 = __float_as_uint(aggT[8 * nt + g][8 * kt + t + 4]);
                mma_tf32(acc[j], a0, a1, a2, a3, b0, b1);
            }
        }
        __syncthreads();   // aggT dead; osm may now overwrite it

        const float b0v = bqo[16 * mt + g];
        const float b1v = bqo[16 * mt + g + 8];
#pragma unroll
        for (int j = 0; j < 2; j++) {
            int pt = 8 * (2 * nh + j) + 2 * t;
            int o  = 16 * mt + g;
            osm[pt][o]         = tanhf(acc[j].x + b0v);
            osm[pt + 1][o]     = tanhf(acc[j].y + b0v);
            osm[pt][o + 8]     = tanhf(acc[j].z + b1v);
            osm[pt + 1][o + 8] = tanhf(acc[j].w + b1v);
        }
    }
    __syncthreads();

    // GRU combine (coalesced loads), update osm in place
    for (int i = tid; i < NPB * HID_; i += 256) {
        int pt = i >> 6, o = i & 63;
        size_t nb = (size_t)(b * N_ + n0 + pt);
        float z  = g_z [nb * HID_ + o];
        float hv = g_hx[nb * C_ + o];
        float qv = osm[pt][o];
        osm[pt][o] = fmaf(z, qv - hv, hv);
    }
    __syncthreads();

    // Phase 3: coalesced transposed output out[b][o][n0..n0+31]
    {
        const int o = tid >> 2;
        const int q = tid & 3;
#pragma unroll
        for (int rep = 0; rep < 2; rep++) {
            int nb = 8 * q + 4 * rep;
            float4 v = make_float4(osm[nb][o], osm[nb + 1][o],
                                   osm[nb + 2][o], osm[nb + 3][o]);
            *(float4*)(out + ((size_t)(b * HID_ + o)) * N_ + n0 + nb) = v;
        }
    }
}

// ---------------------------------------------------------------------------
extern "C" void kernel_launch(void* const* d_in, const int* in_sizes, int n_in,
                              void* d_out, int out_size) {
    const float* xyz = (const float*)d_in[0];
    const float* h   = (const float*)d_in[1];
    const float* x   = (const float*)d_in[2];
    const int*   knn = (const int*)  d_in[3];
    const float* wzp = (const float*)d_in[4];
    const float* bzp = (const float*)d_in[5];
    const float* wzo = (const float*)d_in[6];
    const float* bzo = (const float*)d_in[7];
    const float* wrp = (const float*)d_in[8];
    const float* brp = (const float*)d_in[9];
    const float* wro = (const float*)d_in[10];
    const float* bro = (const float*)d_in[11];
    const float* wqp = (const float*)d_in[12];
    const float* bqp = (const float*)d_in[13];
    const float* wqo = (const float*)d_in[14];
    const float* bqo = (const float*)d_in[15];
    float* out = (float*)d_out;

    k_wT<<<24, 256>>>(wzo, wro, wqo, wzp, bzp, wrp, brp, wqp, bqp);
    k_tr<<<(B_ * N_) / 64, 256>>>(h, x);
    k_zr<<<(B_ * N_) / NPB, 256>>>(xyz, knn, bzo, bro);
    k_q <<<(B_ * N_) / NPB, 256>>>(xyz, knn, bqo, out);
}